// round 11
// baseline (speedup 1.0000x reference)
#include <cuda_runtime.h>
#include <cstdint>

// Fixed problem shapes
static constexpr int B  = 8;
static constexpr int T  = 2048;
static constexpr int D  = 512;
static constexpr int K  = 3;
static constexpr int F  = 512;
static constexpr int BT = B * T;   // 16384 rows
static constexpr int F8 = F / 8;   // 64 float8 per row

static constexpr int TT    = 16;                // t-rows per block
static constexpr int ITERS = (TT * F8) / 256;   // 4

// 256-bit streaming load (LDG.E.256 on sm_10x). 32-byte aligned required.
__device__ __forceinline__ void ldg256_cs(const float* p, uint32_t* v) {
    asm volatile("ld.global.cs.v8.b32 {%0,%1,%2,%3,%4,%5,%6,%7}, [%8];"
                 : "=r"(v[0]), "=r"(v[1]), "=r"(v[2]), "=r"(v[3]),
                   "=r"(v[4]), "=r"(v[5]), "=r"(v[6]), "=r"(v[7])
                 : "l"(p));
}

// 256-bit store (STG.256). Default policy (out may stay L2-resident across replays).
__device__ __forceinline__ void stg256(float* p, const uint32_t* v) {
    asm volatile("st.global.v8.b32 [%0], {%1,%2,%3,%4,%5,%6,%7,%8};"
                 :: "l"(p),
                    "r"(v[0]), "r"(v[1]), "r"(v[2]), "r"(v[3]),
                    "r"(v[4]), "r"(v[5]), "r"(v[6]), "r"(v[7])
                 : "memory");
}

__global__ void __launch_bounds__(256, 3) fused_dynconv_kernel(
    const float* __restrict__ x,
    const float* __restrict__ ker,
    float* __restrict__ out)
{
    __shared__ float s_s[TT + 2];

    const int tid  = threadIdx.x;
    const int bt0  = blockIdx.x * TT;
    const int t0   = bt0 & (T - 1);           // T = 2048, power of 2
    const int warp = tid >> 5;
    const int lane = tid & 31;

    const float* __restrict__ kbf = ker + (size_t)bt0 * (K * F);
    float* __restrict__ obf = out + (size_t)bt0 * F;

    // Iteration geometry: idx = it*256 + tid; r = idx>>6 (4 rows/iter);
    // f8 = idx & 63. kernels addr: kbf + r*K*F + f8*8 + k*F.
    uint32_t ca[8], cb[8], cc[8];
    {
        const int idx = tid;
        const int r = idx >> 6, f8 = idx & 63;
        const float* kr = kbf + (size_t)r * (K * F) + f8 * 8;
        ldg256_cs(kr,           ca);
        ldg256_cs(kr + F,       cb);
        ldg256_cs(kr + 2 * F,   cc);
    }

    // ---- Phase 1: row sums for rows bt0-1 .. bt0+TT (18 rows, 8 warps) ----
    for (int r = warp; r < TT + 2; r += 8) {
        const int tg = t0 - 1 + r;
        float acc = 0.0f;
        if (tg >= 0 && tg < T) {
            const float4* __restrict__ xr =
                reinterpret_cast<const float4*>(x + (size_t)(bt0 - 1 + r) * D);
            float4 v0 = xr[lane];
            float4 v1 = xr[lane + 32];
            float4 v2 = xr[lane + 64];
            float4 v3 = xr[lane + 96];
            acc = ((v0.x + v0.y) + (v0.z + v0.w))
                + ((v1.x + v1.y) + (v1.z + v1.w))
                + ((v2.x + v2.y) + (v2.z + v2.w))
                + ((v3.x + v3.y) + (v3.z + v3.w));
#pragma unroll
            for (int o = 16; o > 0; o >>= 1)
                acc += __shfl_xor_sync(0xffffffffu, acc, o);
        }
        if (lane == 0)
            s_s[r] = acc;
    }
    __syncthreads();

    // ---- Phase 2: depth-1 pipelined combine at float8 granularity ----
#pragma unroll
    for (int it = 0; it < ITERS; ++it) {
        uint32_t na[8], nb[8], nc[8];
        if (it + 1 < ITERS) {
            const int idxn = (it + 1) * 256 + tid;
            const int rn = idxn >> 6, f8n = idxn & 63;
            const float* krn = kbf + (size_t)rn * (K * F) + f8n * 8;
            ldg256_cs(krn,         na);
            ldg256_cs(krn + F,     nb);
            ldg256_cs(krn + 2 * F, nc);
        }

        const int idx = it * 256 + tid;
        const int r   = idx >> 6;
        const float sp = s_s[r];
        const float sc = s_s[r + 1];
        const float sn = s_s[r + 2];

        uint32_t o[8];
#pragma unroll
        for (int j = 0; j < 8; ++j) {
            float a = __uint_as_float(ca[j]);
            float b = __uint_as_float(cb[j]);
            float c = __uint_as_float(cc[j]);
            o[j] = __float_as_uint(fmaf(sp, a, fmaf(sc, b, sn * c)));
        }
        stg256(obf + (size_t)idx * 8, o);

#pragma unroll
        for (int j = 0; j < 8; ++j) { ca[j] = na[j]; cb[j] = nb[j]; cc[j] = nc[j]; }
    }
}

extern "C" void kernel_launch(void* const* d_in, const int* in_sizes, int n_in,
                              void* d_out, int out_size) {
    const float* x   = (const float*)d_in[0];   // [B, T, D]
    const float* ker = (const float*)d_in[1];   // [B, T, K, F]
    float* out = (float*)d_out;                 // [B, T, F]
    (void)in_sizes; (void)n_in; (void)out_size;

    fused_dynconv_kernel<<<BT / TT, 256>>>(x, ker, out);   // 1024 blocks
}

// round 12
// speedup vs baseline: 1.5327x; 1.5327x over previous
#include <cuda_runtime.h>
#include <cstdint>

// Fixed problem shapes
static constexpr int B  = 8;
static constexpr int T  = 2048;
static constexpr int D  = 512;
static constexpr int K  = 3;
static constexpr int F  = 512;
static constexpr int BT = B * T;   // 16384 rows
static constexpr int F4 = F / 4;   // 128 float4 per row

static constexpr int TT    = 16;                // t-rows per block
static constexpr int ITERS = (TT * F4) / 256;   // 8

// Converged configuration (measured twice at 23.04 us):
//  - math reduction: out[b,t,f] = sum_k ker[b,t,k,f] * rowsum(x[b,t+k-1,:])
//    -> pure streaming problem, 164 MB compulsory traffic, HBM-bound
//  - kernels (96 MB, zero reuse) streamed evict-first (__ldcs) so x/out keep L2
//  - x loads + out stores default policy (survive across graph replays in L2)
//  - depth-2 register pipeline + pre-barrier prefetch to cover phase-1 latency
__global__ void __launch_bounds__(256, 4) fused_dynconv_kernel(
    const float* __restrict__ x,
    const float* __restrict__ ker,
    float* __restrict__ out)
{
    __shared__ float s_s[TT + 2];

    const int tid  = threadIdx.x;
    const int bt0  = blockIdx.x * TT;
    const int t0   = bt0 & (T - 1);           // T = 2048, power of 2
    const int warp = tid >> 5;
    const int lane = tid & 31;

    const float4* __restrict__ kb =
        reinterpret_cast<const float4*>(ker + (size_t)bt0 * (K * F));
    float4* __restrict__ ob =
        reinterpret_cast<float4*>(out + (size_t)bt0 * F);

    // ---- Prefetch kernels-loads for iterations 0 and 1 BEFORE the barrier ----
    const int idx0 = tid;
    const int idx1 = 256 + tid;
    const int r0 = idx0 >> 7, f40 = idx0 & (F4 - 1);
    const int r1 = idx1 >> 7, f41 = idx1 & (F4 - 1);
    const float4* kr0 = kb + (size_t)r0 * (K * F4);
    const float4* kr1 = kb + (size_t)r1 * (K * F4);
    float4 pa0 = __ldcs(kr0 + f40);
    float4 pb0 = __ldcs(kr0 + f40 + F4);
    float4 pc0 = __ldcs(kr0 + f40 + 2 * F4);
    float4 pa1 = __ldcs(kr1 + f41);
    float4 pb1 = __ldcs(kr1 + f41 + F4);
    float4 pc1 = __ldcs(kr1 + f41 + 2 * F4);

    // ---- Phase 1: row sums for rows bt0-1 .. bt0+TT (18 rows, 8 warps) ----
    for (int r = warp; r < TT + 2; r += 8) {
        const int tg = t0 - 1 + r;
        float acc = 0.0f;
        if (tg >= 0 && tg < T) {
            const float4* __restrict__ xr =
                reinterpret_cast<const float4*>(x + (size_t)(bt0 - 1 + r) * D);
            float4 v0 = xr[lane];
            float4 v1 = xr[lane + 32];
            float4 v2 = xr[lane + 64];
            float4 v3 = xr[lane + 96];
            acc = ((v0.x + v0.y) + (v0.z + v0.w))
                + ((v1.x + v1.y) + (v1.z + v1.w))
                + ((v2.x + v2.y) + (v2.z + v2.w))
                + ((v3.x + v3.y) + (v3.z + v3.w));
#pragma unroll
            for (int o = 16; o > 0; o >>= 1)
                acc += __shfl_xor_sync(0xffffffffu, acc, o);
        }
        if (lane == 0)
            s_s[r] = acc;
    }
    __syncthreads();

    // ---- Phase 2: depth-2 software-pipelined combine ----
#pragma unroll
    for (int it = 0; it < ITERS; ++it) {
        float4 na, nb, nc;
        if (it + 2 < ITERS) {
            const int idxn = (it + 2) * 256 + tid;
            const int rn = idxn >> 7, f4n = idxn & (F4 - 1);
            const float4* krn = kb + (size_t)rn * (K * F4);
            na = __ldcs(krn + f4n);
            nb = __ldcs(krn + f4n + F4);
            nc = __ldcs(krn + f4n + 2 * F4);
        }

        const int idx = it * 256 + tid;
        const int r   = idx >> 7;
        const float sp = s_s[r];
        const float sc = s_s[r + 1];
        const float sn = s_s[r + 2];

        float4 o;
        o.x = fmaf(sp, pa0.x, fmaf(sc, pb0.x, sn * pc0.x));
        o.y = fmaf(sp, pa0.y, fmaf(sc, pb0.y, sn * pc0.y));
        o.z = fmaf(sp, pa0.z, fmaf(sc, pb0.z, sn * pc0.z));
        o.w = fmaf(sp, pa0.w, fmaf(sc, pb0.w, sn * pc0.w));
        ob[idx] = o;

        pa0 = pa1; pb0 = pb1; pc0 = pc1;
        pa1 = na;  pb1 = nb;  pc1 = nc;
    }
}

extern "C" void kernel_launch(void* const* d_in, const int* in_sizes, int n_in,
                              void* d_out, int out_size) {
    const float* x   = (const float*)d_in[0];   // [B, T, D]
    const float* ker = (const float*)d_in[1];   // [B, T, K, F]
    float* out = (float*)d_out;                 // [B, T, F]
    (void)in_sizes; (void)n_in; (void)out_size;

    fused_dynconv_kernel<<<BT / TT, 256>>>(x, ker, out);   // 1024 blocks
}